// round 6
// baseline (speedup 1.0000x reference)
#include <cuda_runtime.h>
#include <cuda_bf16.h>
#include <cstdint>

#define Bn  32
#define ICn 512
#define OCn 512

// ---------------- device scratch (no allocation allowed) ----------------
__device__ float g_style[Bn * ICn];
__device__ float g_demod[Bn * OCn];
__device__ float g_wsq[OCn * ICn];
// weight tiles: [144 chunks][512 oc][32 k] bf16 (k contiguous), c1 pre-applied
__device__ __align__(16) __nv_bfloat16 g_mwhi[144 * 512 * 32];
__device__ __align__(16) __nv_bfloat16 g_mwlo[144 * 512 * 32];
// modulated input, channel-last: [b][y][x][ic] bf16 hi/lo (x * style)
__device__ __align__(16) __nv_bfloat16 g_xhi[(size_t)Bn * 64 * 64 * 512];
__device__ __align__(16) __nv_bfloat16 g_xlo[(size_t)Bn * 64 * 64 * 512];

// ---------------- prep 1: style MLP + weight hi/lo tiles + wsq ----------------
__global__ void prep1_kernel(const float* __restrict__ w, const float* __restrict__ lin_w,
                             const float* __restrict__ lin_b, const float* __restrict__ conv_w) {
    if (blockIdx.x < 32) {
        // style[b,i] = (1/16) * sum_k w[b,k]*lin_w[i,k] + lin_b[i]
        __shared__ float wv[512];
        int b = blockIdx.x, i = threadIdx.x;
        wv[i] = w[b * 512 + i];
        __syncthreads();
        float acc = 0.f;
        const float* lr = lin_w + i * 512;
#pragma unroll 8
        for (int k = 0; k < 512; k++) acc += wv[k] * lr[k];
        g_style[b * 512 + i] = acc * (1.0f / 16.0f) + lin_b[i];
    } else {
        // weight tiles (c1 = 1/48 applied ONCE here) + wsq on tap==0 threads
        int gid = (blockIdx.x - 32) * 512 + threadIdx.x;   // 4608 blocks * 512
        if (gid >= 144 * 512 * 32) return;
        int icl = gid & 31;
        int oc  = (gid >> 5) & 511;
        int chunk = gid >> 14;
        int icb = chunk / 9, tap = chunk - icb * 9;
        int ic = icb * 32 + icl;
        const float* wp = conv_w + ((size_t)oc * 512 + ic) * 9;
        float v = wp[tap] * (1.0f / 48.0f);
        __nv_bfloat16 hi = __float2bfloat16(v);
        g_mwhi[gid] = hi;
        g_mwlo[gid] = __float2bfloat16(v - __bfloat162float(hi));
        if (tap == 0) {
            float sq = 0.f;
#pragma unroll
            for (int k = 0; k < 9; k++) { float t = wp[k]; sq += t * t; }
            g_wsq[oc * 512 + ic] = sq;
        }
    }
}

// ---------------- prep 2: demod ----------------
__global__ void demod_kernel() {
    __shared__ float s2[512];
    int b = blockIdx.x, o = threadIdx.x;
    float sv = g_style[b * 512 + o];
    s2[o] = sv * sv;
    __syncthreads();
    float acc = 0.f;
    const float* wr = g_wsq + o * 512;
#pragma unroll 8
    for (int i = 0; i < 512; i++) acc += s2[i] * wr[i];
    // demod = rsqrt(c1^2 * sum_i style^2 * wsq + 1e-8), c1^2 = 1/2304
    g_demod[b * 512 + o] = rsqrtf(acc * (1.0f / 2304.0f) + 1e-8f);
}

// ---------------- prep 3: modulated x, transposed to channel-last bf16 hi/lo ----------------
__global__ void xmod_kernel(const float* __restrict__ x) {
    __shared__ float t[32][33];
    int b = blockIdx.z, yx0 = blockIdx.x * 32, ic0 = blockIdx.y * 32;
    int tx = threadIdx.x, ty = threadIdx.y;   // 32 x 8
#pragma unroll
    for (int k = 0; k < 4; k++)
        t[ty + 8 * k][tx] = x[(((size_t)b * 512 + ic0 + ty + 8 * k) << 12) + yx0 + tx];
    __syncthreads();
#pragma unroll
    for (int k = 0; k < 4; k++) {
        int yx = yx0 + ty + 8 * k;
        int ic = ic0 + tx;
        float v = t[tx][ty + 8 * k] * g_style[b * 512 + ic];
        __nv_bfloat16 hi = __float2bfloat16(v);
        size_t o = (((size_t)b << 12) + yx) * 512 + ic;
        g_xhi[o] = hi;
        g_xlo[o] = __float2bfloat16(v - __bfloat162float(hi));
    }
}

// ---------------- main conv (mma.sync implicit GEMM) ----------------
#define MMA16816(d, a, b0_, b1_) \
    asm volatile("mma.sync.aligned.m16n8k16.row.col.f32.bf16.bf16.f32 " \
        "{%0,%1,%2,%3}, {%4,%5,%6,%7}, {%8,%9}, {%0,%1,%2,%3};" \
        : "+f"((d)[0]), "+f"((d)[1]), "+f"((d)[2]), "+f"((d)[3]) \
        : "r"((a)[0]), "r"((a)[1]), "r"((a)[2]), "r"((a)[3]), "r"(b0_), "r"(b1_))

#define AST 40   // smem row stride in bf16 elements (80 bytes)

__device__ __forceinline__ uint32_t lds_pair(const __nv_bfloat16* base, int row, int k) {
    return *(const uint32_t*)((const char*)base + (row * AST + k) * 2);
}

__global__ void __launch_bounds__(256, 2) conv_hmma_kernel(
    const float* __restrict__ noise, const float* __restrict__ bias,
    const float* __restrict__ noise_w, float* __restrict__ out, int b_base)
{
    __shared__ __align__(16) __nv_bfloat16 sAhi[128 * AST];
    __shared__ __align__(16) __nv_bfloat16 sAlo[128 * AST];
    __shared__ __align__(16) __nv_bfloat16 sBhi[128 * AST];
    __shared__ __align__(16) __nv_bfloat16 sBlo[128 * AST];

    const int tid  = threadIdx.x;
    const int lane = tid & 31, wid = tid >> 5;
    const int b   = b_base + blockIdx.z;
    const int oc0 = blockIdx.y * 128;
    const int y0  = blockIdx.x * 2;

    float acc[4][4][4];
#pragma unroll
    for (int a = 0; a < 4; a++)
#pragma unroll
        for (int c = 0; c < 4; c++)
#pragma unroll
            for (int r = 0; r < 4; r++) acc[a][c][r] = 0.f;

    const int p = tid & 127, khalf = tid >> 7;      // A-build role
    const int py = p >> 6, px = p & 63;
    const int wm = wid >> 2, wn = wid & 3;          // warp tile: 64 m x 32 n
    const int gr = lane >> 2, tg = lane & 3;        // fragment lane coords

    for (int icb = 0; icb < 16; icb++) {
        for (int tap = 0; tap < 9; tap++) {
            __syncthreads();   // previous chunk's fragment reads done
            const int kh = tap / 3, kw = tap - kh * 3;
            const int gy = y0 + py + kh - 1, gx = px + kw - 1;
            const bool ok = ((unsigned)gy < 64u) && ((unsigned)gx < 64u);

            // ---- A build: copy precomputed modulated bf16 hi/lo (vectorized) ----
            {
                uint4 h0 = {0,0,0,0}, h1 = {0,0,0,0}, l0 = {0,0,0,0}, l1 = {0,0,0,0};
                if (ok) {
                    size_t xo = (((size_t)b << 12) + gy * 64 + gx) * 512
                              + icb * 32 + khalf * 16;
                    const uint4* ph = (const uint4*)(g_xhi + xo);
                    const uint4* pl = (const uint4*)(g_xlo + xo);
                    h0 = ph[0]; h1 = ph[1];
                    l0 = pl[0]; l1 = pl[1];
                }
                char* dh = (char*)sAhi + p * 80 + khalf * 32;
                char* dl = (char*)sAlo + p * 80 + khalf * 32;
                *(uint4*)dh = h0; *(uint4*)(dh + 16) = h1;
                *(uint4*)dl = l0; *(uint4*)(dl + 16) = l1;
            }
            // ---- B copy: [128 oc][32 k] bf16, coalesced uint4 ----
            {
                const int chunk = icb * 9 + tap;
                const uint4* gh = (const uint4*)(g_mwhi + ((size_t)(chunk * 512 + oc0) * 32));
                const uint4* gl = (const uint4*)(g_mwlo + ((size_t)(chunk * 512 + oc0) * 32));
#pragma unroll
                for (int q = 0; q < 2; q++) {
                    int i4 = tid * 2 + q;            // 512 uint4 per buffer
                    int row = i4 >> 2, seg = i4 & 3;
                    *(uint4*)((char*)sBhi + row * 80 + seg * 16) = gh[i4];
                    *(uint4*)((char*)sBlo + row * 80 + seg * 16) = gl[i4];
                }
            }
            __syncthreads();

            // ---- fragments via direct LDS + 3-pass mma (B outer, A per-mi) ----
#pragma unroll
            for (int ks = 0; ks < 2; ks++) {
                const int kb = ks * 16;
                uint32_t bh[4][2], bl[4][2];
#pragma unroll
                for (int ni = 0; ni < 4; ni++) {
                    int n0 = wn * 32 + ni * 8 + gr;
                    bh[ni][0] = lds_pair(sBhi, n0, kb + tg * 2);
                    bh[ni][1] = lds_pair(sBhi, n0, kb + tg * 2 + 8);
                    bl[ni][0] = lds_pair(sBlo, n0, kb + tg * 2);
                    bl[ni][1] = lds_pair(sBlo, n0, kb + tg * 2 + 8);
                }
#pragma unroll
                for (int mi = 0; mi < 4; mi++) {
                    int r0 = wm * 64 + mi * 16 + gr;
                    uint32_t ah[4], al[4];
                    ah[0] = lds_pair(sAhi, r0,     kb + tg * 2);
                    ah[1] = lds_pair(sAhi, r0 + 8, kb + tg * 2);
                    ah[2] = lds_pair(sAhi, r0,     kb + tg * 2 + 8);
                    ah[3] = lds_pair(sAhi, r0 + 8, kb + tg * 2 + 8);
                    al[0] = lds_pair(sAlo, r0,     kb + tg * 2);
                    al[1] = lds_pair(sAlo, r0 + 8, kb + tg * 2);
                    al[2] = lds_pair(sAlo, r0,     kb + tg * 2 + 8);
                    al[3] = lds_pair(sAlo, r0 + 8, kb + tg * 2 + 8);
#pragma unroll
                    for (int ni = 0; ni < 4; ni++) {
                        MMA16816(acc[mi][ni], ah, bh[ni][0], bh[ni][1]);  // hi*hi
                        MMA16816(acc[mi][ni], ah, bl[ni][0], bl[ni][1]);  // hi*lo
                        MMA16816(acc[mi][ni], al, bh[ni][0], bh[ni][1]);  // lo*hi
                    }
                }
            }
        }
    }

    // ---- epilogue: demod + bias + noise ----
#pragma unroll
    for (int mi = 0; mi < 4; mi++)
#pragma unroll
        for (int ni = 0; ni < 4; ni++) {
            int oc = oc0 + wn * 32 + ni * 8 + tg * 2;
            int m  = wm * 64 + mi * 16 + gr;
            float dm0 = g_demod[b * 512 + oc],  dm1 = g_demod[b * 512 + oc + 1];
            float bs0 = bias[oc],               bs1 = bias[oc + 1];
            float nw0 = noise_w[oc],            nw1 = noise_w[oc + 1];
#pragma unroll
            for (int rr = 0; rr < 2; rr++) {
                int mm = m + rr * 8;
                int yy = y0 + (mm >> 6), xx = mm & 63;
                size_t i0 = ((size_t)(b * 512 + oc) << 12) + yy * 64 + xx;
                size_t i1 = i0 + 4096;
                out[i0] = acc[mi][ni][rr * 2 + 0] * dm0 + bs0 + nw0 * noise[i0];
                out[i1] = acc[mi][ni][rr * 2 + 1] * dm1 + bs1 + nw1 * noise[i1];
            }
        }
}

// ---------------------------------------------------------------------------
// Inputs (metadata order): x, w, conv_w, lin_w, lin_b, bias, noise_w, noise
// ---------------------------------------------------------------------------
extern "C" void kernel_launch(void* const* d_in, const int* in_sizes, int n_in,
                              void* d_out, int out_size) {
    (void)in_sizes; (void)n_in; (void)out_size;
    const float* x       = (const float*)d_in[0];
    const float* w       = (const float*)d_in[1];
    const float* conv_w  = (const float*)d_in[2];
    const float* lin_w   = (const float*)d_in[3];
    const float* lin_b   = (const float*)d_in[4];
    const float* bias    = (const float*)d_in[5];
    const float* noise_w = (const float*)d_in[6];
    const float* noise   = (const float*)d_in[7];
    float* out = (float*)d_out;

    // #1: style + weight tiles + wsq
    prep1_kernel<<<32 + 4608, 512>>>(w, lin_w, lin_b, conv_w);
    // #2: demod
    demod_kernel<<<Bn, 512>>>();
    // #3: modulated channel-last x (tiled transpose)
    {
        dim3 g(128, 16, Bn), t(32, 8);
        xmod_kernel<<<g, t>>>(x);
    }
    // #4..#7: conv, split over batch so ncu (-s 5 -c 1) lands on it
    for (int bb = 0; bb < 4; bb++) {
        dim3 grid(32, 4, 8);
        conv_hmma_kernel<<<grid, 256>>>(noise, bias, noise_w, out, bb * 8);
    }
}

// round 9
// speedup vs baseline: 2.2525x; 2.2525x over previous
#include <cuda_runtime.h>
#include <cuda_fp16.h>
#include <cstdint>

#define Bn  32
#define ICn 512
#define OCn 512

// ---------------- device scratch (no allocation allowed) ----------------
__device__ float g_style[Bn * ICn];
__device__ float g_demod[Bn * OCn];
__device__ float g_wsq[OCn * ICn];
// weights fp16, c1 applied: [72 chunks = icb*9+tap][512 oc][64 k]
__device__ __align__(16) __half g_mw[72 * 512 * 64];
// modulated input fp16 hi/lo, channel-last: [b][yx][ic]
__device__ __align__(16) __half g_xh[(size_t)Bn * 4096 * 512];
__device__ __align__(16) __half g_xl[(size_t)Bn * 4096 * 512];

// ---------------- prep1: style MLP + fp16 weight tiles + wsq ----------------
__global__ void prep1_kernel(const float* __restrict__ w, const float* __restrict__ lin_w,
                             const float* __restrict__ lin_b, const float* __restrict__ conv_w) {
    if (blockIdx.x < 32) {
        __shared__ float wv[512];
        int b = blockIdx.x, i = threadIdx.x;
        wv[i] = w[b * 512 + i];
        __syncthreads();
        float acc = 0.f;
        const float* lr = lin_w + i * 512;
#pragma unroll 8
        for (int k = 0; k < 512; k++) acc += wv[k] * lr[k];
        g_style[b * 512 + i] = acc * (1.0f / 16.0f) + lin_b[i];   // sqrt(2/512)
    } else {
        int gid = (blockIdx.x - 32) * 512 + threadIdx.x;   // over 72*512*64
        if (gid >= 72 * 512 * 64) return;
        int k  = gid & 63;
        int oc = (gid >> 6) & 511;
        int chunk = gid >> 15;
        int icb = chunk / 9, tap = chunk - icb * 9;
        int ic = icb * 64 + k;
        const float* wp = conv_w + ((size_t)oc * 512 + ic) * 9;
        g_mw[gid] = __float2half_rn(wp[tap] * (1.0f / 48.0f));    // c1 = sqrt(2/4608)
        if (tap == 0) {
            float sq = 0.f;
#pragma unroll
            for (int t = 0; t < 9; t++) { float v = wp[t]; sq += v * v; }
            g_wsq[oc * 512 + ic] = sq;
        }
    }
}

// ---------------- prep2: demod + modulated channel-last fp16 hi/lo x ----------------
__global__ void prep2_kernel(const float* __restrict__ x) {
    int tx = threadIdx.x, ty = threadIdx.y;        // 32 x 8
    int t = ty * 32 + tx;
    if (blockIdx.x < 32) {
        // demod[b,o] = rsqrt((1/2304) * sum_i style^2 * wsq + 1e-8)
        __shared__ float s2[512];
        int b = blockIdx.x;
        float sv0 = g_style[b * 512 + t], sv1 = g_style[b * 512 + t + 256];
        s2[t] = sv0 * sv0; s2[t + 256] = sv1 * sv1;
        __syncthreads();
#pragma unroll
        for (int h = 0; h < 2; h++) {
            int o = t + h * 256;
            float acc = 0.f;
            const float* wr = g_wsq + o * 512;
#pragma unroll 8
            for (int i = 0; i < 512; i++) acc += s2[i] * wr[i];
            g_demod[b * 512 + o] = rsqrtf(acc * (1.0f / 2304.0f) + 1e-8f);
        }
    } else {
        // xmod: transpose 32yx x 32ic tile, modulate, fp16 split
        __shared__ float tb[32][33];
        int r = blockIdx.x - 32;                   // 32 b * 128 yx-tiles * 16 ic-tiles
        int b = r >> 11;
        int rr = r & 2047;
        int yx0 = (rr >> 4) * 32, ic0 = (rr & 15) * 32;
#pragma unroll
        for (int k = 0; k < 4; k++)
            tb[ty + 8 * k][tx] = x[((size_t)(b * 512 + ic0 + ty + 8 * k) << 12) + yx0 + tx];
        __syncthreads();
#pragma unroll
        for (int k = 0; k < 4; k++) {
            int yx = yx0 + ty + 8 * k;
            int ic = ic0 + tx;
            float v = tb[tx][ty + 8 * k] * g_style[b * 512 + ic];
            __half hi = __float2half_rn(v);
            size_t o = (((size_t)b << 12) + yx) * 512 + ic;
            g_xh[o] = hi;
            g_xl[o] = __float2half_rn(v - __half2float(hi));
        }
    }
}

// ---------------- main conv: halo-patch implicit GEMM, fp16 2-pass ----------------
#define MMA16816(d, a, b0_, b1_) \
    asm volatile("mma.sync.aligned.m16n8k16.row.col.f32.f16.f16.f32 " \
        "{%0,%1,%2,%3}, {%4,%5,%6,%7}, {%8,%9}, {%0,%1,%2,%3};" \
        : "+f"((d)[0]), "+f"((d)[1]), "+f"((d)[2]), "+f"((d)[3]) \
        : "r"((a)[0]), "r"((a)[1]), "r"((a)[2]), "r"((a)[3]), "r"(b0_), "r"(b1_))

#define PSTB 144                 // patch/B row stride in bytes (72 fp16)
#define PH_OFF 0                 // 204 * 144 = 29376
#define PL_OFF 29376
#define B0_OFF 58752             // 128 * 144 = 18432 per buffer
#define B1_OFF 77184
#define SMEM_CONV 95616

__device__ __forceinline__ uint32_t lds32(const char* p) {
    return *(const uint32_t*)p;
}

__global__ void __launch_bounds__(256, 2) conv_kernel(
    const float* __restrict__ noise, const float* __restrict__ bias,
    const float* __restrict__ noise_w, float* __restrict__ out)
{
    extern __shared__ __align__(16) char smem[];
    char* const pH = smem + PH_OFF;
    char* const pL = smem + PL_OFF;
    char* const pB[2] = { smem + B0_OFF, smem + B1_OFF };

    const int tid  = threadIdx.x;
    const int lane = tid & 31, wid = tid >> 5;
    const int b   = blockIdx.z;
    const int oc0 = blockIdx.y * 128;
    const int mt  = blockIdx.x;
    const int y0  = (mt >> 1) * 4;                // 4 rows x 32 cols output tile
    const int x0  = (mt & 1) * 32;

    const int wm = wid >> 1, wn = wid & 1;        // warp tile 32m x 64n
    const int gr = lane >> 2, tg = lane & 3;

    float acc[2][8][4];
#pragma unroll
    for (int mi = 0; mi < 2; mi++)
#pragma unroll
        for (int ni = 0; ni < 8; ni++)
#pragma unroll
            for (int r = 0; r < 4; r++) acc[mi][ni][r] = 0.f;

    const int u0 = tid;
    const int m0base = wm * 32;

    for (int icb = 0; icb < 8; icb++) {
        // ---- build halo patch (6 x 34 px, 64 ic, hi+lo) ----
#pragma unroll
        for (int q = 0; q < 2; q++) {
            int u = u0 + q * 256;
            if (u < 408) {
                int pp = u >> 1, hf = u & 1;
                int pr = pp / 34, pc = pp - pr * 34;
                int gy = y0 + pr - 1, gx = x0 + pc - 1;
                uint4 h0 = {0,0,0,0}, h1 = {0,0,0,0}, h2 = {0,0,0,0}, h3 = {0,0,0,0};
                uint4 l0 = {0,0,0,0}, l1 = {0,0,0,0}, l2 = {0,0,0,0}, l3 = {0,0,0,0};
                if ((unsigned)gy < 64u && (unsigned)gx < 64u) {
                    size_t xo = (((size_t)b << 12) + gy * 64 + gx) * 512 + icb * 64 + hf * 32;
                    const uint4* ph = (const uint4*)(g_xh + xo);
                    const uint4* pl = (const uint4*)(g_xl + xo);
                    h0 = ph[0]; h1 = ph[1]; h2 = ph[2]; h3 = ph[3];
                    l0 = pl[0]; l1 = pl[1]; l2 = pl[2]; l3 = pl[3];
                }
                char* dh = pH + pp * PSTB + hf * 64;
                char* dl = pL + pp * PSTB + hf * 64;
                ((uint4*)dh)[0] = h0; ((uint4*)dh)[1] = h1; ((uint4*)dh)[2] = h2; ((uint4*)dh)[3] = h3;
                ((uint4*)dl)[0] = l0; ((uint4*)dl)[1] = l1; ((uint4*)dl)[2] = l2; ((uint4*)dl)[3] = l3;
            }
        }
        // ---- B for tap 0 of this icb into buffer 0 (WITH oc0 offset) ----
        {
            const uint4* src = (const uint4*)(g_mw + ((size_t)(icb * 9) * 512 + oc0) * 64);
#pragma unroll
            for (int q = 0; q < 4; q++) {
                int u = q * 256 + tid;                 // 1024 uint4
                int oc = u >> 3, seg = u & 7;
                *(uint4*)(pB[0] + oc * PSTB + seg * 16) = src[u];
            }
        }
        __syncthreads();

        for (int tap = 0; tap < 9; tap++) {
            const int cur = tap & 1;
            // prefetch next tap's B into the other buffer (WITH oc0 offset)
            if (tap < 8) {
                const uint4* src = (const uint4*)(g_mw + ((size_t)(icb * 9 + tap + 1) * 512 + oc0) * 64);
#pragma unroll
                for (int q = 0; q < 4; q++) {
                    int u = q * 256 + tid;
                    int oc = u >> 3, seg = u & 7;
                    *(uint4*)(pB[cur ^ 1] + oc * PSTB + seg * 16) = src[u];
                }
            }
            const int kh = tap / 3, kw = tap - kh * 3;
            const char* bbase = pB[cur];

#pragma unroll
            for (int ks = 0; ks < 4; ks++) {
                const int kb = ks * 32 + tg * 4;       // byte offset of k within row
                uint32_t bh[8][2];
#pragma unroll
                for (int ni = 0; ni < 8; ni++) {
                    int n0 = wn * 64 + ni * 8 + gr;
                    const char* bp = bbase + n0 * PSTB + kb;
                    bh[ni][0] = lds32(bp);
                    bh[ni][1] = lds32(bp + 16);
                }
#pragma unroll
                for (int mi = 0; mi < 2; mi++) {
                    int ma = m0base + mi * 16 + gr;
                    int mb = ma + 8;
                    int ia = ((ma >> 5) + kh) * 34 + (ma & 31) + kw;
                    int ib = ((mb >> 5) + kh) * 34 + (mb & 31) + kw;
                    uint32_t ah[4], al[4];
                    const char* pa = pH + ia * PSTB + kb;
                    const char* pb2 = pH + ib * PSTB + kb;
                    ah[0] = lds32(pa);       ah[1] = lds32(pb2);
                    ah[2] = lds32(pa + 16);  ah[3] = lds32(pb2 + 16);
                    const char* qa = pL + ia * PSTB + kb;
                    const char* qb = pL + ib * PSTB + kb;
                    al[0] = lds32(qa);       al[1] = lds32(qb);
                    al[2] = lds32(qa + 16);  al[3] = lds32(qb + 16);
#pragma unroll
                    for (int ni = 0; ni < 8; ni++)
                        MMA16816(acc[mi][ni], ah, bh[ni][0], bh[ni][1]);   // hi pass
#pragma unroll
                    for (int ni = 0; ni < 8; ni++)
                        MMA16816(acc[mi][ni], al, bh[ni][0], bh[ni][1]);   // lo pass
                }
            }
            __syncthreads();   // B[next] written & B[cur]/patch reads done
        }
    }

    // ---- epilogue: demod + bias + noise ----
#pragma unroll
    for (int mi = 0; mi < 2; mi++)
#pragma unroll
        for (int ni = 0; ni < 8; ni++) {
            int oc = oc0 + wn * 64 + ni * 8 + tg * 2;
            int m  = m0base + mi * 16 + gr;
            float dm0 = g_demod[b * 512 + oc],  dm1 = g_demod[b * 512 + oc + 1];
            float bs0 = bias[oc],               bs1 = bias[oc + 1];
            float nw0 = noise_w[oc],            nw1 = noise_w[oc + 1];
#pragma unroll
            for (int rr = 0; rr < 2; rr++) {
                int mm = m + rr * 8;
                int yy = y0 + (mm >> 5), xx = x0 + (mm & 31);
                size_t i0 = ((size_t)(b * 512 + oc) << 12) + yy * 64 + xx;
                size_t i1 = i0 + 4096;
                out[i0] = acc[mi][ni][rr * 2 + 0] * dm0 + bs0 + nw0 * noise[i0];
                out[i1] = acc[mi][ni][rr * 2 + 1] * dm1 + bs1 + nw1 * noise[i1];
            }
        }
}

// ---------------------------------------------------------------------------
// Inputs (metadata order): x, w, conv_w, lin_w, lin_b, bias, noise_w, noise
// ---------------------------------------------------------------------------
extern "C" void kernel_launch(void* const* d_in, const int* in_sizes, int n_in,
                              void* d_out, int out_size) {
    (void)in_sizes; (void)n_in; (void)out_size;
    const float* x       = (const float*)d_in[0];
    const float* w       = (const float*)d_in[1];
    const float* conv_w  = (const float*)d_in[2];
    const float* lin_w   = (const float*)d_in[3];
    const float* lin_b   = (const float*)d_in[4];
    const float* bias    = (const float*)d_in[5];
    const float* noise_w = (const float*)d_in[6];
    const float* noise   = (const float*)d_in[7];
    float* out = (float*)d_out;

    cudaFuncSetAttribute(conv_kernel, cudaFuncAttributeMaxDynamicSharedMemorySize, SMEM_CONV);

    // #1: style + fp16 weight tiles + wsq
    prep1_kernel<<<32 + 4608, 512>>>(w, lin_w, lin_b, conv_w);
    // #2: demod + xmod (fused)
    {
        dim3 t(32, 8);
        prep2_kernel<<<32 + Bn * 128 * 16, t>>>(x);
    }
    // #3: conv, single launch
    {
        dim3 grid(32, 4, Bn);
        conv_kernel<<<grid, 256, SMEM_CONV>>>(noise, bias, noise_w, out);
    }
}

// round 10
// speedup vs baseline: 2.3619x; 1.0486x over previous
#include <cuda_runtime.h>
#include <cuda_fp16.h>
#include <cstdint>

#define Bn  32
#define ICn 512
#define OCn 512

// ---------------- device scratch (no allocation allowed) ----------------
__device__ float g_style[Bn * ICn];
__device__ float g_demod[Bn * OCn];
__device__ float g_wsq[OCn * ICn];
// weights fp16, c1 applied, k sigma-permuted: [72 chunks][512 oc][64 k]
__device__ __align__(16) __half g_mw[72 * 512 * 64];
// modulated input fp16 hi/lo, channel-last, ic sigma-permuted per 16-group
__device__ __align__(16) __half g_xh[(size_t)Bn * 4096 * 512];
__device__ __align__(16) __half g_xl[(size_t)Bn * 4096 * 512];

// sigma: within a 16-k group, storage position of logical k j, such that the
// m16n8k16 fragment halves (2t,2t+1,2t+8,2t+9) for thread-group t are the
// contiguous 8 bytes at storage offset 8t.
__host__ __device__ __forceinline__ int sigma16(int j) {
    return ((j & 7) >> 1) * 4 + ((j >> 3) & 1) * 2 + (j & 1);
}
__host__ __device__ __forceinline__ int ksig(int k) {   // within 64
    return (k & 48) | sigma16(k & 15);
}

// ---------------- prep1: style MLP (blocks 0..31) + weights (one oc/block) ----------------
__global__ void prep1_kernel(const float* __restrict__ w, const float* __restrict__ lin_w,
                             const float* __restrict__ lin_b, const float* __restrict__ conv_w) {
    if (blockIdx.x < 32) {
        __shared__ float wv[512];
        int b = blockIdx.x, i = threadIdx.x;
        wv[i] = w[b * 512 + i];
        __syncthreads();
        float acc = 0.f;
        const float* lr = lin_w + i * 512;
#pragma unroll 8
        for (int k = 0; k < 512; k++) acc += wv[k] * lr[k];
        g_style[b * 512 + i] = acc * (1.0f / 16.0f) + lin_b[i];   // sqrt(2/512)
    } else {
        int oc = blockIdx.x - 32;          // 512 blocks
        int ic = threadIdx.x;              // 512 threads, contiguous conv_w reads
        const float* wp = conv_w + ((size_t)oc * 512 + ic) * 9;
        float v[9];
        float sq = 0.f;
#pragma unroll
        for (int t = 0; t < 9; t++) { v[t] = wp[t]; sq += v[t] * v[t]; }
        g_wsq[oc * 512 + ic] = sq;
        int icb = ic >> 6, k = ic & 63;
        int ks = ksig(k);
#pragma unroll
        for (int t = 0; t < 9; t++)
            g_mw[(size_t)(icb * 9 + t) * 32768 + oc * 64 + ks] =
                __float2half_rn(v[t] * (1.0f / 48.0f));           // c1 = sqrt(2/4608)
    }
}

// ---------------- prep2: demod + modulated channel-last fp16 hi/lo x ----------------
__global__ void prep2_kernel(const float* __restrict__ x) {
    int tx = threadIdx.x, ty = threadIdx.y;        // 32 x 8
    int t = ty * 32 + tx;
    if (blockIdx.x < 32) {
        __shared__ float s2[512];
        int b = blockIdx.x;
        float sv0 = g_style[b * 512 + t], sv1 = g_style[b * 512 + t + 256];
        s2[t] = sv0 * sv0; s2[t + 256] = sv1 * sv1;
        __syncthreads();
#pragma unroll
        for (int h = 0; h < 2; h++) {
            int o = t + h * 256;
            float acc = 0.f;
            const float* wr = g_wsq + o * 512;
#pragma unroll 8
            for (int i = 0; i < 512; i++) acc += s2[i] * wr[i];
            g_demod[b * 512 + o] = rsqrtf(acc * (1.0f / 2304.0f) + 1e-8f);
        }
    } else {
        __shared__ float tb[32][33];
        int r = blockIdx.x - 32;
        int b = r >> 11;
        int rr = r & 2047;
        int yx0 = (rr >> 4) * 32, ic0 = (rr & 15) * 32;
#pragma unroll
        for (int k = 0; k < 4; k++)
            tb[ty + 8 * k][tx] = x[((size_t)(b * 512 + ic0 + ty + 8 * k) << 12) + yx0 + tx];
        __syncthreads();
#pragma unroll
        for (int k = 0; k < 4; k++) {
            int yx = yx0 + ty + 8 * k;
            int ic = ic0 + tx;
            float v = tb[tx][ty + 8 * k] * g_style[b * 512 + ic];
            __half hi = __float2half_rn(v);
            int ics = (ic & ~15) | sigma16(ic & 15);   // sigma-permuted channel slot
            size_t o = (((size_t)b << 12) + yx) * 512 + ics;
            g_xh[o] = hi;
            g_xl[o] = __float2half_rn(v - __half2float(hi));
        }
    }
}

// ---------------- main conv: halo-patch implicit GEMM, fp16 2-pass ----------------
#define MMA16816(d, a, b0_, b1_) \
    asm volatile("mma.sync.aligned.m16n8k16.row.col.f32.f16.f16.f32 " \
        "{%0,%1,%2,%3}, {%4,%5,%6,%7}, {%8,%9}, {%0,%1,%2,%3};" \
        : "+f"((d)[0]), "+f"((d)[1]), "+f"((d)[2]), "+f"((d)[3]) \
        : "r"((a)[0]), "r"((a)[1]), "r"((a)[2]), "r"((a)[3]), "r"(b0_), "r"(b1_))

#define CP16(dst, src, sz) \
    asm volatile("cp.async.cg.shared.global [%0], [%1], 16, %2;" \
                 :: "r"(dst), "l"(src), "r"(sz) : "memory")
#define CP_COMMIT() asm volatile("cp.async.commit_group;" ::: "memory")
#define CP_WAIT0()  asm volatile("cp.async.wait_group 0;" ::: "memory")

#define PSTB 144                 // patch/B row stride in bytes (72 fp16)
#define PH_OFF 0                 // 204 * 144 = 29376
#define PL_OFF 29376
#define B0_OFF 58752             // 128 * 144 = 18432 per buffer
#define B1_OFF 77184
#define SMEM_CONV 95616

__device__ __forceinline__ uint32_t smem_u32(const void* p) {
    uint32_t a;
    asm("{ .reg .u64 t; cvta.to.shared.u64 t, %1; cvt.u32.u64 %0, t; }" : "=r"(a) : "l"(p));
    return a;
}
__device__ __forceinline__ uint2 lds64(const char* p) {
    return *(const uint2*)p;
}

__global__ void __launch_bounds__(256, 2) conv_kernel(
    const float* __restrict__ noise, const float* __restrict__ bias,
    const float* __restrict__ noise_w, float* __restrict__ out)
{
    extern __shared__ __align__(16) char smem[];
    char* const pH = smem + PH_OFF;
    char* const pL = smem + PL_OFF;
    char* const pB[2] = { smem + B0_OFF, smem + B1_OFF };
    const uint32_t uH = smem_u32(smem) + PH_OFF;
    const uint32_t uL = smem_u32(smem) + PL_OFF;
    const uint32_t uB[2] = { smem_u32(smem) + B0_OFF, smem_u32(smem) + B1_OFF };

    const int tid  = threadIdx.x;
    const int lane = tid & 31, wid = tid >> 5;
    const int b   = blockIdx.z;
    const int oc0 = blockIdx.y * 128;
    const int mt  = blockIdx.x;
    const int y0  = (mt >> 1) * 4;                // 4 rows x 32 cols output tile
    const int x0  = (mt & 1) * 32;

    const int wm = wid >> 1, wn = wid & 1;        // warp tile 32m x 64n
    const int gr = lane >> 2, tg = lane & 3;

    float acc[2][8][4];
#pragma unroll
    for (int mi = 0; mi < 2; mi++)
#pragma unroll
        for (int ni = 0; ni < 8; ni++)
#pragma unroll
            for (int r = 0; r < 4; r++) acc[mi][ni][r] = 0.f;

    const int m0base = wm * 32;

    for (int icb = 0; icb < 8; icb++) {
        // ---- patch (6 x 34 px, 64 ic, hi+lo) via cp.async ----
#pragma unroll
        for (int q = 0; q < 2; q++) {
            int u = tid + q * 256;
            if (u < 408) {
                int pp = u >> 1, hf = u & 1;
                int pr = pp / 34, pc = pp - pr * 34;
                int gy = y0 + pr - 1, gx = x0 + pc - 1;
                bool ok = ((unsigned)gy < 64u) && ((unsigned)gx < 64u);
                uint32_t sz = ok ? 16u : 0u;
                size_t xo = ok ? ((((size_t)b << 12) + gy * 64 + gx) * 512
                                  + icb * 64 + hf * 32) : 0;
                const char* sh = (const char*)(g_xh + xo);
                const char* sl = (const char*)(g_xl + xo);
                uint32_t dh = uH + pp * PSTB + hf * 64;
                uint32_t dl = uL + pp * PSTB + hf * 64;
#pragma unroll
                for (int s = 0; s < 4; s++) {
                    CP16(dh + s * 16, sh + s * 16, sz);
                    CP16(dl + s * 16, sl + s * 16, sz);
                }
            }
        }
        // ---- B tap 0 via cp.async ----
        {
            const char* src = (const char*)(g_mw + ((size_t)(icb * 9) * 512 + oc0) * 64);
#pragma unroll
            for (int q = 0; q < 4; q++) {
                int u = q * 256 + tid;                 // 1024 x 16B
                int oc = u >> 3, seg = u & 7;
                CP16(uB[0] + oc * PSTB + seg * 16, src + u * 16, 16u);
            }
        }
        CP_COMMIT();
        CP_WAIT0();
        __syncthreads();

        for (int tap = 0; tap < 9; tap++) {
            const int cur = tap & 1;
            // prefetch next tap's B
            if (tap < 8) {
                const char* src = (const char*)(g_mw + ((size_t)(icb * 9 + tap + 1) * 512 + oc0) * 64);
#pragma unroll
                for (int q = 0; q < 4; q++) {
                    int u = q * 256 + tid;
                    int oc = u >> 3, seg = u & 7;
                    CP16(uB[cur ^ 1] + oc * PSTB + seg * 16, src + u * 16, 16u);
                }
                CP_COMMIT();
            }
            const int kh = tap / 3, kw = tap - kh * 3;
            const char* bbase = pB[cur];

#pragma unroll
            for (int ks = 0; ks < 4; ks++) {
                const int kb = ks * 32 + tg * 8;       // sigma layout: one 8B word
                uint2 bf[8];
#pragma unroll
                for (int ni = 0; ni < 8; ni++) {
                    int n0 = wn * 64 + ni * 8 + gr;
                    bf[ni] = lds64(bbase + n0 * PSTB + kb);
                }
#pragma unroll
                for (int mi = 0; mi < 2; mi++) {
                    int ma = m0base + mi * 16 + gr;
                    int mb = ma + 8;
                    int ia = ((ma >> 5) + kh) * 34 + (ma & 31) + kw;
                    int ib = ((mb >> 5) + kh) * 34 + (mb & 31) + kw;
                    uint2 aha = lds64(pH + ia * PSTB + kb);   // (a0, a2)
                    uint2 ahb = lds64(pH + ib * PSTB + kb);   // (a1, a3)
                    uint2 ala = lds64(pL + ia * PSTB + kb);
                    uint2 alb = lds64(pL + ib * PSTB + kb);
                    uint32_t ah[4] = { aha.x, ahb.x, aha.y, ahb.y };
                    uint32_t al[4] = { ala.x, alb.x, ala.y, alb.y };
#pragma unroll
                    for (int ni = 0; ni < 8; ni++)
                        MMA16816(acc[mi][ni], ah, bf[ni].x, bf[ni].y);   // hi pass
#pragma unroll
                    for (int ni = 0; ni < 8; ni++)
                        MMA16816(acc[mi][ni], al, bf[ni].x, bf[ni].y);   // lo pass
                }
            }
            CP_WAIT0();
            __syncthreads();   // B[next] landed & B[cur]/patch reads done
        }
    }

    // ---- epilogue: demod + bias + noise ----
#pragma unroll
    for (int mi = 0; mi < 2; mi++)
#pragma unroll
        for (int ni = 0; ni < 8; ni++) {
            int oc = oc0 + wn * 64 + ni * 8 + tg * 2;
            int m  = m0base + mi * 16 + gr;
            float dm0 = g_demod[b * 512 + oc],  dm1 = g_demod[b * 512 + oc + 1];
            float bs0 = bias[oc],               bs1 = bias[oc + 1];
            float nw0 = noise_w[oc],            nw1 = noise_w[oc + 1];
#pragma unroll
            for (int rr = 0; rr < 2; rr++) {
                int mm = m + rr * 8;
                int yy = y0 + (mm >> 5), xx = x0 + (mm & 31);
                size_t i0 = ((size_t)(b * 512 + oc) << 12) + yy * 64 + xx;
                size_t i1 = i0 + 4096;
                out[i0] = acc[mi][ni][rr * 2 + 0] * dm0 + bs0 + nw0 * noise[i0];
                out[i1] = acc[mi][ni][rr * 2 + 1] * dm1 + bs1 + nw1 * noise[i1];
            }
        }
}

// ---------------------------------------------------------------------------
// Inputs (metadata order): x, w, conv_w, lin_w, lin_b, bias, noise_w, noise
// ---------------------------------------------------------------------------
extern "C" void kernel_launch(void* const* d_in, const int* in_sizes, int n_in,
                              void* d_out, int out_size) {
    (void)in_sizes; (void)n_in; (void)out_size;
    const float* x       = (const float*)d_in[0];
    const float* w       = (const float*)d_in[1];
    const float* conv_w  = (const float*)d_in[2];
    const float* lin_w   = (const float*)d_in[3];
    const float* lin_b   = (const float*)d_in[4];
    const float* bias    = (const float*)d_in[5];
    const float* noise_w = (const float*)d_in[6];
    const float* noise   = (const float*)d_in[7];
    float* out = (float*)d_out;

    cudaFuncSetAttribute(conv_kernel, cudaFuncAttributeMaxDynamicSharedMemorySize, SMEM_CONV);

    // #1: style + fp16 weight tiles (sigma-permuted) + wsq
    prep1_kernel<<<32 + 512, 512>>>(w, lin_w, lin_b, conv_w);
    // #2: demod + xmod (sigma-permuted channel-last)
    {
        dim3 t(32, 8);
        prep2_kernel<<<32 + Bn * 128 * 16, t>>>(x);
    }
    // #3: conv
    {
        dim3 grid(32, 4, Bn);
        conv_kernel<<<grid, 256, SMEM_CONV>>>(noise, bias, noise_w, out);
    }
}

// round 12
// speedup vs baseline: 3.5052x; 1.4841x over previous
#include <cuda_runtime.h>
#include <cuda_fp16.h>
#include <cstdint>

#define Bn  32
#define ICn 512
#define OCn 512

// ---------------- device scratch (no allocation allowed) ----------------
__device__ float g_style[Bn * ICn];
__device__ float g_demod[Bn * OCn];
__device__ float g_wsq[OCn * ICn];
// weights fp16, c1 applied, k sigma-permuted: [72 chunks][512 oc][64 k]
__device__ __align__(16) __half g_mw[72 * 512 * 64];
// modulated input fp16, channel-last, ic sigma-permuted per 16-group
__device__ __align__(16) __half g_xh[(size_t)Bn * 4096 * 512];

// sigma: within a 16-k group, storage position of logical k j, such that the
// m16n8k16 fragment halves (2t,2t+1,2t+8,2t+9) for thread-group t are the
// contiguous 8 bytes at storage offset 8t.
__host__ __device__ __forceinline__ int sigma16(int j) {
    return ((j & 7) >> 1) * 4 + ((j >> 3) & 1) * 2 + (j & 1);
}

// ---------------- prep1: style MLP + weights (32B-contiguous stores) + wsq ----------------
__global__ void prep1_kernel(const float* __restrict__ w, const float* __restrict__ lin_w,
                             const float* __restrict__ lin_b, const float* __restrict__ conv_w) {
    int blk = blockIdx.x, tid = threadIdx.x;       // 256 threads
    if (blk < 32) {
        // style[b,i] = (1/16) * sum_k w[b,k]*lin_w[i,k] + lin_b[i]
        __shared__ float wv[512];
        int b = blk;
        wv[tid] = w[b * 512 + tid];
        wv[tid + 256] = w[b * 512 + tid + 256];
        __syncthreads();
#pragma unroll
        for (int h = 0; h < 2; h++) {
            int i = tid + h * 256;
            float acc = 0.f;
            const float* lr = lin_w + i * 512;
#pragma unroll 8
            for (int k = 0; k < 512; k++) acc += wv[k] * lr[k];
            g_style[b * 512 + i] = acc * (1.0f / 16.0f) + lin_b[i];
        }
    } else if (blk < 608) {
        // weight tiles: one 16-k group per thread -> one contiguous 32B store
        int t = (blk - 32) * 256 + tid;            // [0, 147456)
        int kg = t & 3;
        int oc = (t >> 2) & 511;
        int chunk = t >> 11;                       // [0,72) = icb*9+tap
        int icb = chunk / 9, tap = chunk - icb * 9;
        __half hbuf[16];
#pragma unroll
        for (int j = 0; j < 16; j++) {
            float v = conv_w[((size_t)oc * 512 + icb * 64 + kg * 16 + j) * 9 + tap];
            hbuf[sigma16(j)] = __float2half_rn(v * (1.0f / 48.0f));   // c1 = sqrt(2/4608)
        }
        uint4* dst = (uint4*)(g_mw + (size_t)chunk * 32768 + oc * 64 + kg * 16);
        dst[0] = ((uint4*)hbuf)[0];
        dst[1] = ((uint4*)hbuf)[1];
    } else {
        // wsq[oc][ic]
        int u = (blk - 608) * 256 + tid;           // [0, 262144)
        int oc = u >> 9, ic = u & 511;
        const float* wp = conv_w + ((size_t)oc * 512 + ic) * 9;
        float sq = 0.f;
#pragma unroll
        for (int t9 = 0; t9 < 9; t9++) { float v = wp[t9]; sq += v * v; }
        g_wsq[oc * 512 + ic] = sq;
    }
}

// ---------------- prep2: demod + modulated channel-last fp16 x ----------------
__global__ void prep2_kernel(const float* __restrict__ x) {
    int tx = threadIdx.x, ty = threadIdx.y;        // 32 x 8
    int t = ty * 32 + tx;
    if (blockIdx.x < 32) {
        __shared__ float s2[512];
        int b = blockIdx.x;
        float sv0 = g_style[b * 512 + t], sv1 = g_style[b * 512 + t + 256];
        s2[t] = sv0 * sv0; s2[t + 256] = sv1 * sv1;
        __syncthreads();
#pragma unroll
        for (int h = 0; h < 2; h++) {
            int o = t + h * 256;
            float acc = 0.f;
            const float* wr = g_wsq + o * 512;
#pragma unroll 8
            for (int i = 0; i < 512; i++) acc += s2[i] * wr[i];
            g_demod[b * 512 + o] = rsqrtf(acc * (1.0f / 2304.0f) + 1e-8f);
        }
    } else {
        __shared__ float tb[32][33];
        int r = blockIdx.x - 32;
        int b = r >> 11;
        int rr = r & 2047;
        int yx0 = (rr >> 4) * 32, ic0 = (rr & 15) * 32;
#pragma unroll
        for (int k = 0; k < 4; k++)
            tb[ty + 8 * k][tx] = x[((size_t)(b * 512 + ic0 + ty + 8 * k) << 12) + yx0 + tx];
        __syncthreads();
#pragma unroll
        for (int k = 0; k < 4; k++) {
            int yx = yx0 + ty + 8 * k;
            int ic = ic0 + tx;
            float v = tb[tx][ty + 8 * k] * g_style[b * 512 + ic];
            int ics = (ic & ~15) | sigma16(ic & 15);   // sigma-permuted channel slot
            g_xh[(((size_t)b << 12) + yx) * 512 + ics] = __float2half_rn(v);
        }
    }
}

// ---------------- main conv: halo-patch implicit GEMM, fp16 1-pass ----------------
#define MMA16816(d, a, b0_, b1_) \
    asm volatile("mma.sync.aligned.m16n8k16.row.col.f32.f16.f16.f32 " \
        "{%0,%1,%2,%3}, {%4,%5,%6,%7}, {%8,%9}, {%0,%1,%2,%3};" \
        : "+f"((d)[0]), "+f"((d)[1]), "+f"((d)[2]), "+f"((d)[3]) \
        : "r"((a)[0]), "r"((a)[1]), "r"((a)[2]), "r"((a)[3]), "r"(b0_), "r"(b1_))

#define CP16(dst, src, sz) \
    asm volatile("cp.async.cg.shared.global [%0], [%1], 16, %2;" \
                 :: "r"(dst), "l"(src), "r"(sz) : "memory")
#define CP_COMMIT() asm volatile("cp.async.commit_group;" ::: "memory")
#define CP_WAIT0()  asm volatile("cp.async.wait_group 0;" ::: "memory")

#define PSTB 144                 // patch/B row stride in bytes (72 fp16)
#define PH_OFF 0                 // 204 * 144 = 29376
#define B0_OFF 29376             // 128 * 144 = 18432 per buffer
#define B1_OFF 47808
#define SMEM_CONV 66240

__device__ __forceinline__ uint32_t smem_u32(const void* p) {
    uint32_t a;
    asm("{ .reg .u64 t; cvta.to.shared.u64 t, %1; cvt.u32.u64 %0, t; }" : "=r"(a) : "l"(p));
    return a;
}
__device__ __forceinline__ uint2 lds64(const char* p) {
    return *(const uint2*)p;
}

__global__ void __launch_bounds__(256, 2) conv_kernel(
    const float* __restrict__ noise, const float* __restrict__ bias,
    const float* __restrict__ noise_w, float* __restrict__ out)
{
    extern __shared__ __align__(16) char smem[];
    char* const pH = smem + PH_OFF;
    char* const pB[2] = { smem + B0_OFF, smem + B1_OFF };
    const uint32_t uH = smem_u32(smem) + PH_OFF;
    const uint32_t uB[2] = { smem_u32(smem) + B0_OFF, smem_u32(smem) + B1_OFF };

    const int tid  = threadIdx.x;
    const int lane = tid & 31, wid = tid >> 5;
    const int b   = blockIdx.z;
    const int oc0 = blockIdx.y * 128;
    const int mt  = blockIdx.x;
    const int y0  = (mt >> 1) * 4;                // 4 rows x 32 cols output tile
    const int x0  = (mt & 1) * 32;

    const int wm = wid >> 1, wn = wid & 1;        // warp tile 32m x 64n
    const int gr = lane >> 2, tg = lane & 3;

    float acc[2][8][4];
#pragma unroll
    for (int mi = 0; mi < 2; mi++)
#pragma unroll
        for (int ni = 0; ni < 8; ni++)
#pragma unroll
            for (int r = 0; r < 4; r++) acc[mi][ni][r] = 0.f;

    const int m0base = wm * 32;

    for (int icb = 0; icb < 8; icb++) {
        // ---- patch (6 x 34 px, 64 ic) via cp.async: 408 units of 32B ----
#pragma unroll
        for (int q = 0; q < 2; q++) {
            int u = tid + q * 256;
            if (u < 408) {
                int pp = u >> 1, hf = u & 1;
                int pr = pp / 34, pc = pp - pr * 34;
                int gy = y0 + pr - 1, gx = x0 + pc - 1;
                bool ok = ((unsigned)gy < 64u) && ((unsigned)gx < 64u);
                uint32_t sz = ok ? 16u : 0u;
                size_t xo = ok ? ((((size_t)b << 12) + gy * 64 + gx) * 512
                                  + icb * 64 + hf * 32) : 0;
                const char* sh = (const char*)(g_xh + xo);
                uint32_t dh = uH + pp * PSTB + hf * 64;
#pragma unroll
                for (int s = 0; s < 4; s++) CP16(dh + s * 16, sh + s * 16, sz);
            }
        }
        // ---- B tap 0 via cp.async ----
        {
            const char* src = (const char*)(g_mw + ((size_t)(icb * 9) * 512 + oc0) * 64);
#pragma unroll
            for (int q = 0; q < 4; q++) {
                int u = q * 256 + tid;                 // 1024 x 16B
                int oc = u >> 3, seg = u & 7;
                CP16(uB[0] + oc * PSTB + seg * 16, src + u * 16, 16u);
            }
        }
        CP_COMMIT();
        CP_WAIT0();
        __syncthreads();

        for (int tap = 0; tap < 9; tap++) {
            const int cur = tap & 1;
            // prefetch next tap's B
            if (tap < 8) {
                const char* src = (const char*)(g_mw + ((size_t)(icb * 9 + tap + 1) * 512 + oc0) * 64);
#pragma unroll
                for (int q = 0; q < 4; q++) {
                    int u = q * 256 + tid;
                    int oc = u >> 3, seg = u & 7;
                    CP16(uB[cur ^ 1] + oc * PSTB + seg * 16, src + u * 16, 16u);
                }
                CP_COMMIT();
            }
            const int kh = tap / 3, kw = tap - kh * 3;
            const char* bbase = pB[cur];

#pragma unroll
            for (int ks = 0; ks < 4; ks++) {
                const int kb = ks * 32 + tg * 8;       // sigma layout: one 8B word
                uint2 bf[8];
#pragma unroll
                for (int ni = 0; ni < 8; ni++) {
                    int n0 = wn * 64 + ni * 8 + gr;
                    bf[ni] = lds64(bbase + n0 * PSTB + kb);
                }
#pragma unroll
                for (int mi = 0; mi < 2; mi++) {
                    int ma = m0base + mi * 16 + gr;
                    int mb = ma + 8;
                    int ia = ((ma >> 5) + kh) * 34 + (ma & 31) + kw;
                    int ib = ((mb >> 5) + kh) * 34 + (mb & 31) + kw;
                    uint2 aha = lds64(pH + ia * PSTB + kb);   // (a0, a2)
                    uint2 ahb = lds64(pH + ib * PSTB + kb);   // (a1, a3)
                    uint32_t ah[4] = { aha.x, ahb.x, aha.y, ahb.y };
#pragma unroll
                    for (int ni = 0; ni < 8; ni++)
                        MMA16816(acc[mi][ni], ah, bf[ni].x, bf[ni].y);
                }
            }
            CP_WAIT0();
            __syncthreads();   // B[next] landed & B[cur]/patch reads done
        }
    }

    // ---- epilogue: demod + bias + noise ----
#pragma unroll
    for (int mi = 0; mi < 2; mi++)
#pragma unroll
        for (int ni = 0; ni < 8; ni++) {
            int oc = oc0 + wn * 64 + ni * 8 + tg * 2;
            int m  = m0base + mi * 16 + gr;
            float dm0 = g_demod[b * 512 + oc],  dm1 = g_demod[b * 512 + oc + 1];
            float bs0 = bias[oc],               bs1 = bias[oc + 1];
            float nw0 = noise_w[oc],            nw1 = noise_w[oc + 1];
#pragma unroll
            for (int rr = 0; rr < 2; rr++) {
                int mm = m + rr * 8;
                int yy = y0 + (mm >> 5), xx = x0 + (mm & 31);
                size_t i0 = ((size_t)(b * 512 + oc) << 12) + yy * 64 + xx;
                size_t i1 = i0 + 4096;
                out[i0] = acc[mi][ni][rr * 2 + 0] * dm0 + bs0 + nw0 * noise[i0];
                out[i1] = acc[mi][ni][rr * 2 + 1] * dm1 + bs1 + nw1 * noise[i1];
            }
        }
}

// ---------------------------------------------------------------------------
// Inputs (metadata order): x, w, conv_w, lin_w, lin_b, bias, noise_w, noise
// ---------------------------------------------------------------------------
extern "C" void kernel_launch(void* const* d_in, const int* in_sizes, int n_in,
                              void* d_out, int out_size) {
    (void)in_sizes; (void)n_in; (void)out_size;
    const float* x       = (const float*)d_in[0];
    const float* w       = (const float*)d_in[1];
    const float* conv_w  = (const float*)d_in[2];
    const float* lin_w   = (const float*)d_in[3];
    const float* lin_b   = (const float*)d_in[4];
    const float* bias    = (const float*)d_in[5];
    const float* noise_w = (const float*)d_in[6];
    const float* noise   = (const float*)d_in[7];
    float* out = (float*)d_out;

    cudaFuncSetAttribute(conv_kernel, cudaFuncAttributeMaxDynamicSharedMemorySize, SMEM_CONV);

    // #1: style + fp16 weight tiles (sigma, 32B stores) + wsq
    prep1_kernel<<<32 + 576 + 1024, 256>>>(w, lin_w, lin_b, conv_w);
    // #2: demod + xmod (sigma-permuted channel-last fp16)
    {
        dim3 t(32, 8);
        prep2_kernel<<<32 + Bn * 128 * 16, t>>>(x);
    }
    // #3: conv
    {
        dim3 grid(32, 4, Bn);
        conv_kernel<<<grid, 256, SMEM_CONV>>>(noise, bias, noise_w, out);
    }
}

// round 13
// speedup vs baseline: 3.6661x; 1.0459x over previous
#include <cuda_runtime.h>
#include <cuda_fp16.h>
#include <cstdint>

#define Bn  32
#define ICn 512
#define OCn 512

// ---------------- device scratch (no allocation allowed) ----------------
__device__ float g_style[Bn * ICn];
__device__ float g_demod[Bn * OCn];
__device__ float g_wsq[OCn * ICn];
// weights fp16, c1 applied, k sigma-permuted: [72 chunks][512 oc][64 k]
__device__ __align__(16) __half g_mw[72 * 512 * 64];
// modulated input fp16, channel-last, ic sigma-permuted per 16-group
__device__ __align__(16) __half g_xh[(size_t)Bn * 4096 * 512];

// sigma: within a 16-k group, storage position of logical k j, such that the
// m16n8k16 fragment halves (2t,2t+1,2t+8,2t+9) for thread-group t are the
// contiguous 8 bytes at storage offset 8t.
__host__ __device__ __forceinline__ int sigma16(int j) {
    return ((j & 7) >> 1) * 4 + ((j >> 3) & 1) * 2 + (j & 1);
}

// ---------------- prep1: style MLP + per-oc smem-staged weight tiles + wsq ----------------
__global__ void prep1_kernel(const float* __restrict__ w, const float* __restrict__ lin_w,
                             const float* __restrict__ lin_b, const float* __restrict__ conv_w) {
    __shared__ float cw[4608];
    int blk = blockIdx.x, tid = threadIdx.x;       // 256 threads
    if (blk < 32) {
        // style[b,i] = (1/16) * sum_k w[b,k]*lin_w[i,k] + lin_b[i]
        int b = blk;
        cw[tid] = w[b * 512 + tid];
        cw[tid + 256] = w[b * 512 + tid + 256];
        __syncthreads();
#pragma unroll
        for (int h = 0; h < 2; h++) {
            int i = tid + h * 256;
            float acc = 0.f;
            const float* lr = lin_w + i * 512;
#pragma unroll 8
            for (int k = 0; k < 512; k++) acc += cw[k] * lr[k];
            g_style[b * 512 + i] = acc * (1.0f / 16.0f) + lin_b[i];
        }
    } else {
        // one oc per block: coalesced stage of conv_w[oc] (512x9 floats)
        int oc = blk - 32;
        const float* src = conv_w + (size_t)oc * 4608;
        for (int i = tid; i < 4608; i += 256) cw[i] = src[i];
        __syncthreads();
        // wsq
#pragma unroll
        for (int h = 0; h < 2; h++) {
            int ic = tid + h * 256;
            float sq = 0.f;
#pragma unroll
            for (int t = 0; t < 9; t++) { float v = cw[ic * 9 + t]; sq += v * v; }
            g_wsq[oc * 512 + ic] = sq;
        }
        // weight tiles: 288 16-k groups, one contiguous 32B store each
        for (int g = tid; g < 288; g += 256) {
            int chunk = g >> 2, kg = g & 3;        // chunk = icb*9+tap
            int icb = chunk / 9, tap = chunk - icb * 9;
            __half hbuf[16];
#pragma unroll
            for (int j = 0; j < 16; j++)
                hbuf[sigma16(j)] = __float2half_rn(
                    cw[(icb * 64 + kg * 16 + j) * 9 + tap] * (1.0f / 48.0f));  // c1
            uint4* dst = (uint4*)(g_mw + (size_t)chunk * 32768 + oc * 64 + kg * 16);
            dst[0] = ((uint4*)hbuf)[0];
            dst[1] = ((uint4*)hbuf)[1];
        }
    }
}

// ---------------- prep2: demod + modulated channel-last fp16 x ----------------
__global__ void prep2_kernel(const float* __restrict__ x) {
    int tx = threadIdx.x, ty = threadIdx.y;        // 32 x 8
    int t = ty * 32 + tx;
    if (blockIdx.x < 32) {
        __shared__ float s2[512];
        int b = blockIdx.x;
        float sv0 = g_style[b * 512 + t], sv1 = g_style[b * 512 + t + 256];
        s2[t] = sv0 * sv0; s2[t + 256] = sv1 * sv1;
        __syncthreads();
#pragma unroll
        for (int h = 0; h < 2; h++) {
            int o = t + h * 256;
            float acc = 0.f;
            const float* wr = g_wsq + o * 512;
#pragma unroll 8
            for (int i = 0; i < 512; i++) acc += s2[i] * wr[i];
            g_demod[b * 512 + o] = rsqrtf(acc * (1.0f / 2304.0f) + 1e-8f);
        }
    } else {
        __shared__ float tb[32][33];
        int r = blockIdx.x - 32;
        int b = r >> 11;
        int rr = r & 2047;
        int yx0 = (rr >> 4) * 32, ic0 = (rr & 15) * 32;
#pragma unroll
        for (int k = 0; k < 4; k++)
            tb[ty + 8 * k][tx] = x[((size_t)(b * 512 + ic0 + ty + 8 * k) << 12) + yx0 + tx];
        __syncthreads();
#pragma unroll
        for (int k = 0; k < 4; k++) {
            int yx = yx0 + ty + 8 * k;
            int ic = ic0 + tx;
            float v = tb[tx][ty + 8 * k] * g_style[b * 512 + ic];
            int ics = (ic & ~15) | sigma16(ic & 15);
            g_xh[(((size_t)b << 12) + yx) * 512 + ics] = __float2half_rn(v);
        }
    }
}

// ---------------- main conv: halo-patch implicit GEMM, fp16 1-pass, 4-deep B ring ----------------
#define MMA16816(d, a, b0_, b1_) \
    asm volatile("mma.sync.aligned.m16n8k16.row.col.f32.f16.f16.f32 " \
        "{%0,%1,%2,%3}, {%4,%5,%6,%7}, {%8,%9}, {%0,%1,%2,%3};" \
        : "+f"((d)[0]), "+f"((d)[1]), "+f"((d)[2]), "+f"((d)[3]) \
        : "r"((a)[0]), "r"((a)[1]), "r"((a)[2]), "r"((a)[3]), "r"(b0_), "r"(b1_))

#define CP16(dst, src, sz) \
    asm volatile("cp.async.cg.shared.global [%0], [%1], 16, %2;" \
                 :: "r"(dst), "l"(src), "r"(sz) : "memory")
#define CP_COMMIT() asm volatile("cp.async.commit_group;" ::: "memory")
#define CP_WAIT0()  asm volatile("cp.async.wait_group 0;" ::: "memory")
#define CP_WAIT2()  asm volatile("cp.async.wait_group 2;" ::: "memory")

#define PSTB 144                 // patch/B row stride in bytes (72 fp16)
#define PH_OFF 0                 // 204 * 144 = 29376
#define BB_SZ  18432             // 128 * 144 per buffer
#define B0_OFF 29376
#define SMEM_CONV (29376 + 4 * 18432)   // 103104

__device__ __forceinline__ uint32_t smem_u32(const void* p) {
    uint32_t a;
    asm("{ .reg .u64 t; cvta.to.shared.u64 t, %1; cvt.u32.u64 %0, t; }" : "=r"(a) : "l"(p));
    return a;
}
__device__ __forceinline__ uint2 lds64(const char* p) {
    return *(const uint2*)p;
}

__global__ void __launch_bounds__(256, 2) conv_kernel(
    const float* __restrict__ noise, const float* __restrict__ bias,
    const float* __restrict__ noise_w, float* __restrict__ out)
{
    extern __shared__ __align__(16) char smem[];
    char* const pH = smem + PH_OFF;
    const uint32_t uS = smem_u32(smem);
    const uint32_t uH = uS + PH_OFF;

    const int tid  = threadIdx.x;
    const int lane = tid & 31, wid = tid >> 5;
    const int b   = blockIdx.z;
    const int oc0 = blockIdx.y * 128;
    const int mt  = blockIdx.x;
    const int y0  = (mt >> 1) * 4;                // 4 rows x 32 cols output tile
    const int x0  = (mt & 1) * 32;

    const int wm = wid >> 1, wn = wid & 1;        // warp tile 32m x 64n
    const int gr = lane >> 2, tg = lane & 3;

    float acc[2][8][4];
#pragma unroll
    for (int mi = 0; mi < 2; mi++)
#pragma unroll
        for (int ni = 0; ni < 8; ni++)
#pragma unroll
            for (int r = 0; r < 4; r++) acc[mi][ni][r] = 0.f;

    const int m0base = wm * 32;

    // B copy role (per thread, fixed): 4 x 16B units per buffer fill
    const int bq_oc[4] = { (0 * 256 + tid) >> 3, (1 * 256 + tid) >> 3,
                           (2 * 256 + tid) >> 3, (3 * 256 + tid) >> 3 };
    const int bq_sg[4] = { tid & 7, tid & 7, tid & 7, tid & 7 };

    for (int icb = 0; icb < 8; icb++) {
        __syncthreads();   // all reads of patch & B ring from prev icb done
        // ---- patch (6 x 34 px, 64 ic) + B taps 0,1 via one cp.async group ----
#pragma unroll
        for (int q = 0; q < 2; q++) {
            int u = tid + q * 256;
            if (u < 408) {
                int pp = u >> 1, hf = u & 1;
                int pr = pp / 34, pc = pp - pr * 34;
                int gy = y0 + pr - 1, gx = x0 + pc - 1;
                bool ok = ((unsigned)gy < 64u) && ((unsigned)gx < 64u);
                uint32_t sz = ok ? 16u : 0u;
                size_t xo = ok ? ((((size_t)b << 12) + gy * 64 + gx) * 512
                                  + icb * 64 + hf * 32) : 0;
                const char* sh = (const char*)(g_xh + xo);
                uint32_t dh = uH + pp * PSTB + hf * 64;
#pragma unroll
                for (int s = 0; s < 4; s++) CP16(dh + s * 16, sh + s * 16, sz);
            }
        }
#pragma unroll
        for (int tp = 0; tp < 2; tp++) {
            const char* src = (const char*)(g_mw + ((size_t)(icb * 9 + tp) * 512 + oc0) * 64);
            uint32_t dB = uS + B0_OFF + tp * BB_SZ;
#pragma unroll
            for (int q = 0; q < 4; q++) {
                int u = q * 256 + tid;
                CP16(dB + bq_oc[q] * PSTB + bq_sg[q] * 16, src + u * 16, 16u);
            }
        }
        CP_COMMIT();
        CP_WAIT0();
        __syncthreads();

        for (int tap = 0; tap < 9; tap++) {
            if (tap && !(tap & 1)) __syncthreads();   // every even tap: ring reuse safe
            // prefetch tap+2's B into buf (tap+2)&3
            if (tap + 2 < 9) {
                const char* src = (const char*)(g_mw + ((size_t)(icb * 9 + tap + 2) * 512 + oc0) * 64);
                uint32_t dB = uS + B0_OFF + ((tap + 2) & 3) * BB_SZ;
#pragma unroll
                for (int q = 0; q < 4; q++) {
                    int u = q * 256 + tid;
                    CP16(dB + bq_oc[q] * PSTB + bq_sg[q] * 16, src + u * 16, 16u);
                }
                CP_COMMIT();
            }
            CP_WAIT2();    // retires exactly the group carrying this tap's B
            const int kh = tap / 3, kw = tap - kh * 3;
            const char* bbase = smem + B0_OFF + (tap & 3) * BB_SZ;

#pragma unroll
            for (int ks = 0; ks < 4; ks++) {
                const int kb = ks * 32 + tg * 8;       // sigma layout: one 8B word
                uint2 bf[8];
#pragma unroll
                for (int ni = 0; ni < 8; ni++) {
                    int n0 = wn * 64 + ni * 8 + gr;
                    bf[ni] = lds64(bbase + n0 * PSTB + kb);
                }
#pragma unroll
                for (int mi = 0; mi < 2; mi++) {
                    int ma = m0base + mi * 16 + gr;
                    int mb = ma + 8;
                    int ia = ((ma >> 5) + kh) * 34 + (ma & 31) + kw;
                    int ib = ((mb >> 5) + kh) * 34 + (mb & 31) + kw;
                    uint2 aha = lds64(pH + ia * PSTB + kb);   // (a0, a2)
                    uint2 ahb = lds64(pH + ib * PSTB + kb);   // (a1, a3)
                    uint32_t ah[4] = { aha.x, ahb.x, aha.y, ahb.y };
#pragma unroll
                    for (int ni = 0; ni < 8; ni++)
                        MMA16816(acc[mi][ni], ah, bf[ni].x, bf[ni].y);
                }
            }
        }
    }

    // ---- epilogue: demod + bias + noise ----
#pragma unroll
    for (int mi = 0; mi < 2; mi++)
#pragma unroll
        for (int ni = 0; ni < 8; ni++) {
            int oc = oc0 + wn * 64 + ni * 8 + tg * 2;
            int m  = m0base + mi * 16 + gr;
            float dm0 = g_demod[b * 512 + oc],  dm1 = g_demod[b * 512 + oc + 1];
            float bs0 = bias[oc],               bs1 = bias[oc + 1];
            float nw0 = noise_w[oc],            nw1 = noise_w[oc + 1];
#pragma unroll
            for (int rr = 0; rr < 2; rr++) {
                int mm = m + rr * 8;
                int yy = y0 + (mm >> 5), xx = x0 + (mm & 31);
                size_t i0 = ((size_t)(b * 512 + oc) << 12) + yy * 64 + xx;
                size_t i1 = i0 + 4096;
                out[i0] = acc[mi][ni][rr * 2 + 0] * dm0 + bs0 + nw0 * noise[i0];
                out[i1] = acc[mi][ni][rr * 2 + 1] * dm1 + bs1 + nw1 * noise[i1];
            }
        }
}

// ---------------------------------------------------------------------------
// Inputs (metadata order): x, w, conv_w, lin_w, lin_b, bias, noise_w, noise
// ---------------------------------------------------------------------------
extern "C" void kernel_launch(void* const* d_in, const int* in_sizes, int n_in,
                              void* d_out, int out_size) {
    (void)in_sizes; (void)n_in; (void)out_size;
    const float* x       = (const float*)d_in[0];
    const float* w       = (const float*)d_in[1];
    const float* conv_w  = (const float*)d_in[2];
    const float* lin_w   = (const float*)d_in[3];
    const float* lin_b   = (const float*)d_in[4];
    const float* bias    = (const float*)d_in[5];
    const float* noise_w = (const float*)d_in[6];
    const float* noise   = (const float*)d_in[7];
    float* out = (float*)d_out;

    cudaFuncSetAttribute(conv_kernel, cudaFuncAttributeMaxDynamicSharedMemorySize, SMEM_CONV);

    // #1: style + weight tiles (smem-staged, coalesced) + wsq
    prep1_kernel<<<32 + 512, 256>>>(w, lin_w, lin_b, conv_w);
    // #2: demod + xmod (sigma-permuted channel-last fp16)
    {
        dim3 t(32, 8);
        prep2_kernel<<<32 + Bn * 128 * 16, t>>>(x);
    }
    // #3: conv
    {
        dim3 grid(32, 4, Bn);
        conv_kernel<<<grid, 256, SMEM_CONV>>>(noise, bias, noise_w, out);
    }
}